// round 4
// baseline (speedup 1.0000x reference)
#include <cuda_runtime.h>
#include <math.h>

#define GRID_R 128
#define NCELL (GRID_R*GRID_R*GRID_R)

// 128^3 cells x 8 channels (7 used + 1 pad) = 64 MiB static scratch
__device__ float g_grid[NCELL * 8];

__device__ __forceinline__ float gelu_f(float x) {
    // jax.nn.gelu approximate=True (tanh form)
    float t = tanhf(0.7978845608028654f * (x + 0.044715f * x * x * x));
    return 0.5f * x * (1.0f + t);
}

// ---------------------------------------------------------------------------
// Kernel 1: zero the grid
// ---------------------------------------------------------------------------
__global__ void zero_grid_kernel() {
    unsigned i = blockIdx.x * blockDim.x + threadIdx.x;
    if (i < (unsigned)(NCELL * 2)) {  // NCELL*8 floats = NCELL*2 float4
        reinterpret_cast<float4*>(g_grid)[i] = make_float4(0.f, 0.f, 0.f, 0.f);
    }
}

// ---------------------------------------------------------------------------
// Kernel 2: particle-to-grid trilinear scatter (vector reductions)
// ---------------------------------------------------------------------------
__device__ __forceinline__ void red_add_v4(float* addr, float a, float b, float c, float d) {
    asm volatile("red.global.add.v4.f32 [%0], {%1,%2,%3,%4};"
                 :: "l"(addr), "f"(a), "f"(b), "f"(c), "f"(d) : "memory");
}

__global__ void p2g_kernel(const float* __restrict__ src_ref,
                           const float* __restrict__ src_curr,
                           const float* __restrict__ Wf,
                           const float* __restrict__ bf,
                           int N) {
    int i = blockIdx.x * blockDim.x + threadIdx.x;
    if (i >= N) return;

    float xs0 = fminf(fmaxf(src_ref[3 * i + 0], 0.f), 1.f);
    float xs1 = fminf(fmaxf(src_ref[3 * i + 1], 0.f), 1.f);
    float xs2 = fminf(fmaxf(src_ref[3 * i + 2], 0.f), 1.f);
    float u0 = src_curr[3 * i + 0] - xs0;
    float u1 = src_curr[3 * i + 1] - xs1;
    float u2 = src_curr[3 * i + 2] - xs2;

    // f_trans = gelu(u @ W_f + b_f), W_f is (3,3) row-major [in][out]
    float f0 = gelu_f(bf[0] + u0 * Wf[0] + u1 * Wf[3] + u2 * Wf[6]);
    float f1 = gelu_f(bf[1] + u0 * Wf[1] + u1 * Wf[4] + u2 * Wf[7]);
    float f2 = gelu_f(bf[2] + u0 * Wf[2] + u1 * Wf[5] + u2 * Wf[8]);

    float cx = fminf(xs0 * 127.f, 126.999f);
    float cy = fminf(xs1 * 127.f, 126.999f);
    float cz = fminf(xs2 * 127.f, 126.999f);
    int bx = (int)cx, by = (int)cy, bz = (int)cz;  // floor (values >= 0)
    float dx = cx - (float)bx, dy = cy - (float)by, dz = cz - (float)bz;

#pragma unroll
    for (int ox = 0; ox < 2; ox++) {
        float wx = ox ? dx : 1.f - dx;
#pragma unroll
        for (int oy = 0; oy < 2; oy++) {
            float wxy = wx * (oy ? dy : 1.f - dy);
#pragma unroll
            for (int oz = 0; oz < 2; oz++) {
                float w = wxy * (oz ? dz : 1.f - dz);
                int cell = ((((bx + ox) << 7) + (by + oy)) << 7) + (bz + oz);
                float* p = g_grid + cell * 8;
                red_add_v4(p,     f0 * w, f1 * w, f2 * w, w);
                red_add_v4(p + 4, u0 * w, u1 * w, u2 * w, 0.f);
            }
        }
    }
}

// ---------------------------------------------------------------------------
// threefry2x32 with key = (0, 42), matching jax.random.key(42)
// ---------------------------------------------------------------------------
__device__ __forceinline__ void tf_round(unsigned& v0, unsigned& v1, int r) {
    v0 += v1;
    v1 = __funnelshift_l(v1, v1, r);  // rotl
    v1 ^= v0;
}

__device__ __forceinline__ uint2 threefry_0_42(unsigned x0, unsigned x1) {
    const unsigned k0 = 0u, k1 = 42u;
    const unsigned k2 = 0u ^ 42u ^ 0x1BD11BDAu;
    unsigned v0 = x0 + k0, v1 = x1 + k1;
    tf_round(v0, v1, 13); tf_round(v0, v1, 15); tf_round(v0, v1, 26); tf_round(v0, v1, 6);
    v0 += k1; v1 += k2 + 1u;
    tf_round(v0, v1, 17); tf_round(v0, v1, 29); tf_round(v0, v1, 16); tf_round(v0, v1, 24);
    v0 += k2; v1 += k0 + 2u;
    tf_round(v0, v1, 13); tf_round(v0, v1, 15); tf_round(v0, v1, 26); tf_round(v0, v1, 6);
    v0 += k0; v1 += k1 + 3u;
    tf_round(v0, v1, 17); tf_round(v0, v1, 29); tf_round(v0, v1, 16); tf_round(v0, v1, 24);
    v0 += k1; v1 += k2 + 4u;
    tf_round(v0, v1, 13); tf_round(v0, v1, 15); tf_round(v0, v1, 26); tf_round(v0, v1, 6);
    v0 += k2; v1 += k0 + 5u;
    return make_uint2(v0, v1);
}

// jax_threefry_partitionable=True (modern JAX default):
// bits[j] = w0 ^ w1 of threefry2x32(key, (j >> 32, j & 0xffffffff)); here j < 2^32.
__device__ __forceinline__ unsigned tf_bits_partitionable(unsigned j) {
    uint2 r = threefry_0_42(0u, j);
    return r.x ^ r.y;
}

__device__ __forceinline__ float bits_to_normal(unsigned b) {
    // JAX: float in [1,2) from top 23 bits, minus 1 -> [0,1)
    float f = __uint_as_float((b >> 9) | 0x3f800000u) - 1.0f;
    // u = f*(hi-lo)+lo with lo=nextafter(-1,0); hi-lo rounds to exactly 2.0f
    float u = f * 2.0f - 0.99999994f;
    u = fmaxf(u, -0.99999994f);
    return 1.4142135623730951f * erfinvf(u);
}

// ---------------------------------------------------------------------------
// Kernel 3: per-query noise gen + 8-path trilinear gather + MLP decode
// ---------------------------------------------------------------------------
__global__ __launch_bounds__(256) void query_kernel(
    const float* __restrict__ xq_in,
    const float* __restrict__ W1, const float* __restrict__ b1,
    const float* __restrict__ W2, const float* __restrict__ b2,
    const float* __restrict__ W3, const float* __restrict__ b3,
    float* __restrict__ out, int M) {

    // Weights in smem, TRANSPOSED so the per-output-neuron inner loop reads
    // contiguous float4 (4 FMA per LDS.128 broadcast -> FFMA-bound, not LDS-bound)
    __shared__ float sW1t[24 * 64];   // [j][i] i contiguous (24 floats = 96B, 16B aligned)
    __shared__ float sW2t[64 * 64];   // [j][i]
    __shared__ float sW3p[64 * 4];    // [j][c] padded to 4
    __shared__ float sb1[64], sb2[64], sb3[3];

    for (int t = threadIdx.x; t < 24 * 64; t += blockDim.x) {
        int j = t / 24, i = t % 24;
        sW1t[t] = W1[i * 64 + j];
    }
    for (int t = threadIdx.x; t < 64 * 64; t += blockDim.x) {
        int j = t >> 6, i = t & 63;
        sW2t[t] = W2[i * 64 + j];
    }
    for (int t = threadIdx.x; t < 192; t += blockDim.x) {
        int j = t / 3, c = t % 3;
        sW3p[j * 4 + c] = W3[t];
    }
    for (int t = threadIdx.x; t < 64; t += blockDim.x) {
        sb1[t] = b1[t];
        sb2[t] = b2[t];
    }
    if (threadIdx.x < 3) sb3[threadIdx.x] = b3[threadIdx.x];
    __syncthreads();

    int m = blockIdx.x * blockDim.x + threadIdx.x;
    if (m >= M) return;

    float xq0 = fminf(fmaxf(xq_in[3 * m + 0], 0.f), 1.f);
    float xq1 = fminf(fmaxf(xq_in[3 * m + 1], 0.f), 1.f);
    float xq2 = fminf(fmaxf(xq_in[3 * m + 2], 0.f), 1.f);
    float q0 = xq0 * 127.f, q1 = xq1 * 127.f, q2 = xq2 * 127.f;

    float a0 = 0.f, a1 = 0.f, a2 = 0.f, a3 = 0.f, a4 = 0.f, a5 = 0.f, a6 = 0.f;

#pragma unroll 1
    for (int kk = 0; kk < 8; kk++) {
        // flat index into noise tensor of shape (8, M, 3): j = (kk*M + m)*3 + c
        unsigned jbase = ((unsigned)kk * (unsigned)M + (unsigned)m) * 3u;
        float px = q0 + 0.8f * bits_to_normal(tf_bits_partitionable(jbase + 0u));
        float py = q1 + 0.8f * bits_to_normal(tf_bits_partitionable(jbase + 1u));
        float pz = q2 + 0.8f * bits_to_normal(tf_bits_partitionable(jbase + 2u));

        float fx = floorf(px), fy = floorf(py), fz = floorf(pz);
        float dx = px - fx, dy = py - fy, dz = pz - fz;
        int lx = (int)fx, ly = (int)fy, lz = (int)fz;
        int x0i = min(max(lx, 0), 127), x1i = min(max(lx + 1, 0), 127);
        int y0i = min(max(ly, 0), 127), y1i = min(max(ly + 1, 0), 127);
        int z0i = min(max(lz, 0), 127), z1i = min(max(lz + 1, 0), 127);
#pragma unroll
        for (int cx = 0; cx < 2; cx++) {
            int ix = cx ? x1i : x0i;
            float wx = cx ? dx : 1.f - dx;
#pragma unroll
            for (int cy = 0; cy < 2; cy++) {
                int iy = cy ? y1i : y0i;
                float wxy = wx * (cy ? dy : 1.f - dy);
#pragma unroll
                for (int cz = 0; cz < 2; cz++) {
                    int iz = cz ? z1i : z0i;
                    float w = wxy * (cz ? dz : 1.f - dz);
                    int cell = (((ix << 7) + iy) << 7) + iz;
                    const float4* g = reinterpret_cast<const float4*>(g_grid) + cell * 2;
                    float4 va = __ldg(g);
                    float4 vb = __ldg(g + 1);
                    a0 += va.x * w; a1 += va.y * w; a2 += va.z * w; a3 += va.w * w;
                    a4 += vb.x * w; a5 += vb.y * w; a6 += vb.z * w;
                }
            }
        }
    }

    // raw = acc/8 ; denom = max(raw_d, 1e-5); mask = raw_d > 1e-5
    float r3 = a3 * 0.125f;
    float denom = fmaxf(r3, 1e-5f);
    float s = (r3 > 1e-5f) ? (0.125f / denom) : 0.f;

    float dec[24];
    dec[0] = a0 * s; dec[1] = a1 * s; dec[2] = a2 * s;
    float un0 = a4 * s, un1 = a5 * s, un2 = a6 * s;
    dec[3] = un0; dec[4] = un1; dec[5] = un2;

    const float PI = 3.14159265358979323846f;
    float sn, cs;
    sincosf(PI * xq0, &sn, &cs);        dec[6]  = sn; dec[9]  = cs;
    sincosf(PI * xq1, &sn, &cs);        dec[7]  = sn; dec[10] = cs;
    sincosf(PI * xq2, &sn, &cs);        dec[8]  = sn; dec[11] = cs;
    sincosf(2.f * PI * xq0, &sn, &cs);  dec[12] = sn; dec[15] = cs;
    sincosf(2.f * PI * xq1, &sn, &cs);  dec[13] = sn; dec[16] = cs;
    sincosf(2.f * PI * xq2, &sn, &cs);  dec[14] = sn; dec[17] = cs;
    sincosf(4.f * PI * xq0, &sn, &cs);  dec[18] = sn; dec[21] = cs;
    sincosf(4.f * PI * xq1, &sn, &cs);  dec[19] = sn; dec[22] = cs;
    sincosf(4.f * PI * xq2, &sn, &cs);  dec[20] = sn; dec[23] = cs;

    // Layer 1: 24 -> 64 (full unroll so h1 stays register-resident)
    float h1v[64];
#pragma unroll
    for (int j = 0; j < 64; j++) {
        const float4* w = reinterpret_cast<const float4*>(sW1t + j * 24);
        float t = sb1[j];
#pragma unroll
        for (int i4 = 0; i4 < 6; i4++) {
            float4 wv = w[i4];
            t += dec[i4 * 4 + 0] * wv.x;
            t += dec[i4 * 4 + 1] * wv.y;
            t += dec[i4 * 4 + 2] * wv.z;
            t += dec[i4 * 4 + 3] * wv.w;
        }
        h1v[j] = gelu_f(t);
    }

    // Layer 2 (64->64) fused with layer 3 (64->3)
    float r0 = sb3[0], r1 = sb3[1], r2 = sb3[2];
#pragma unroll 4
    for (int j = 0; j < 64; j++) {
        const float4* w = reinterpret_cast<const float4*>(sW2t + j * 64);
        float t = sb2[j];
#pragma unroll
        for (int i4 = 0; i4 < 16; i4++) {
            float4 wv = w[i4];
            t += h1v[i4 * 4 + 0] * wv.x;
            t += h1v[i4 * 4 + 1] * wv.y;
            t += h1v[i4 * 4 + 2] * wv.z;
            t += h1v[i4 * 4 + 3] * wv.w;
        }
        float g = gelu_f(t);
        r0 += g * sW3p[j * 4 + 0];
        r1 += g * sW3p[j * 4 + 1];
        r2 += g * sW3p[j * 4 + 2];
    }

    out[3 * m + 0] = fminf(fmaxf(un0 + r0, 0.001f), 0.999f);
    out[3 * m + 1] = fminf(fmaxf(un1 + r1, 0.001f), 0.999f);
    out[3 * m + 2] = fminf(fmaxf(un2 + r2, 0.001f), 0.999f);
}

// ---------------------------------------------------------------------------
extern "C" void kernel_launch(void* const* d_in, const int* in_sizes, int n_in,
                              void* d_out, int out_size) {
    const float* xq  = (const float*)d_in[0];
    const float* xsr = (const float*)d_in[1];
    const float* xsc = (const float*)d_in[2];
    const float* Wf  = (const float*)d_in[3];
    const float* bf  = (const float*)d_in[4];
    const float* W1  = (const float*)d_in[5];
    const float* b1  = (const float*)d_in[6];
    const float* W2  = (const float*)d_in[7];
    const float* b2  = (const float*)d_in[8];
    const float* W3  = (const float*)d_in[9];
    const float* b3  = (const float*)d_in[10];
    int M = in_sizes[0] / 3;
    int N = in_sizes[1] / 3;

    zero_grid_kernel<<<(NCELL * 2 + 255) / 256, 256>>>();
    p2g_kernel<<<(N + 255) / 256, 256>>>(xsr, xsc, Wf, bf, N);
    query_kernel<<<(M + 255) / 256, 256>>>(xq, W1, b1, W2, b2, W3, b3,
                                           (float*)d_out, M);
}